// round 10
// baseline (speedup 1.0000x reference)
#include <cuda_runtime.h>
#include <math.h>

#define N_NODES 100000
#define N_EDGES 1600000
#define FDIM 128
#define NG 64
#define NL 20
#define SCAN_NB 391   // ceil(100000/256)

// ---------------- device scratch ----------------
__device__ float g_h0[N_NODES * FDIM];
__device__ float g_h1[N_NODES * FDIM];
__device__ float g_agg[N_NODES * FDIM];
__device__ int   g_deg[N_NODES];
__device__ int   g_rowstart[N_NODES + 1];
__device__ int   g_cursor[N_NODES];
__device__ int   g_esrc[N_EDGES];
__device__ int   g_blocksums[512];
__device__ int   g_gmax[NG * FDIM];   // float bits; relu outputs >= 0 so int-max == float-max
__device__ float g_gsum[NG * FDIM];
__device__ float g_z[NG * NL];

// ---------------- f32x2 helpers (FFMA2 path, PTX-only) ----------------
__device__ __forceinline__ unsigned long long pk2(float a) {
    unsigned long long r;
    asm("mov.b64 %0, {%1, %1};" : "=l"(r) : "f"(a));
    return r;
}
__device__ __forceinline__ void fma2(unsigned long long& d, unsigned long long a,
                                     unsigned long long b) {
    asm("fma.rn.f32x2 %0, %1, %2, %0;" : "+l"(d) : "l"(a), "l"(b));
}
__device__ __forceinline__ float2 up2(unsigned long long v) {
    float2 f;
    asm("mov.b64 {%0, %1}, %2;" : "=f"(f.x), "=f"(f.y) : "l"(v));
    return f;
}

// ---------------- CSR build ----------------
__global__ void k_count(const int* __restrict__ dst) {
    int e = blockIdx.x * blockDim.x + threadIdx.x;
    if (e < N_EDGES) {
        int d = dst[e];
        atomicAdd(&g_deg[d], 1);
        atomicAdd(&g_blocksums[d >> 8], 1);
    }
}

__device__ __forceinline__ int block_scan_inc(int v, int* warpbuf) {
    int tid = threadIdx.x, lane = tid & 31, wid = tid >> 5;
#pragma unroll
    for (int off = 1; off < 32; off <<= 1) {
        int t = __shfl_up_sync(0xffffffffu, v, off);
        if (lane >= off) v += t;
    }
    if (lane == 31) warpbuf[wid] = v;
    __syncthreads();
    if (wid == 0) {
        int nw = blockDim.x >> 5;
        int w = (lane < nw) ? warpbuf[lane] : 0;
#pragma unroll
        for (int off = 1; off < 32; off <<= 1) {
            int t = __shfl_up_sync(0xffffffffu, w, off);
            if (lane >= off) w += t;
        }
        warpbuf[lane] = w;
    }
    __syncthreads();
    return v + (wid > 0 ? warpbuf[wid - 1] : 0);
}

__global__ void k_scan23() {
    __shared__ int wb[32];
    __shared__ int s_off;
    int tid = threadIdx.x;
    int i = blockIdx.x * blockDim.x + tid;
    int v = (i < N_NODES) ? g_deg[i] : 0;
    int inc = block_scan_inc(v, wb);
    if (tid < 32) {
        int p = 0;
        for (int j = tid; j < blockIdx.x; j += 32) p += g_blocksums[j];
#pragma unroll
        for (int off = 16; off > 0; off >>= 1)
            p += __shfl_down_sync(0xffffffffu, p, off);
        if (tid == 0) s_off = p;
    }
    __syncthreads();
    if (i < N_NODES) {
        int ex = s_off + inc - v;
        g_rowstart[i] = ex;
        g_cursor[i] = ex;
        if (i == N_NODES - 1) g_rowstart[N_NODES] = ex + v;
    }
}

__global__ void k_fill(const int* __restrict__ src, const int* __restrict__ dst) {
    int e = blockIdx.x * blockDim.x + threadIdx.x;
    if (e >= N_EDGES) return;
    int d = dst[e];
    int pos = atomicAdd(&g_cursor[d], 1);
    g_esrc[pos] = src[e];
}

// ---------------- embedding gather (s2; feeds layer-1 root GEMM) ----------
__global__ void k_gather(const int* __restrict__ x, const float4* __restrict__ emb) {
    int idx = blockIdx.x * blockDim.x + threadIdx.x;
    if (idx >= N_NODES * 32) return;
    int node = idx >> 5;
    int c = idx & 31;
    ((float4*)g_h0)[idx] = emb[(size_t)x[node] * 32 + c];
}

// ---- layer-1 aggregation from L2-resident emb (measured 57us, 3 rounds) ----
__device__ __forceinline__ void agg_accum4(float4& acc, const float4* __restrict__ tab,
                                           int a0, int a1, int a2, int a3, int lane) {
    float4 v0 = tab[(size_t)a0 * 32 + lane];
    float4 v1 = tab[(size_t)a1 * 32 + lane];
    float4 v2 = tab[(size_t)a2 * 32 + lane];
    float4 v3 = tab[(size_t)a3 * 32 + lane];
    acc.x += (v0.x + v1.x) + (v2.x + v3.x);
    acc.y += (v0.y + v1.y) + (v2.y + v3.y);
    acc.z += (v0.z + v1.z) + (v2.z + v3.z);
    acc.w += (v0.w + v1.w) + (v2.w + v3.w);
}

__global__ void k_agg_emb(const int* __restrict__ x, const float4* __restrict__ emb) {
    int w = (blockIdx.x * blockDim.x + threadIdx.x) >> 5;
    int lane = threadIdx.x & 31;
    if (w >= N_NODES) return;
    int s = g_rowstart[w], e = g_rowstart[w + 1];
    float4 acc = make_float4(0.f, 0.f, 0.f, 0.f);
    for (int i = s; i < e; i += 32) {
        int cnt = min(32, e - i);
        int idx = g_esrc[i + ((lane < cnt) ? lane : 0)];
        int xs = x[idx];
        if (cnt == 32) {
#pragma unroll
            for (int j = 0; j < 32; j += 4) {
                int a0 = __shfl_sync(0xffffffffu, xs, j);
                int a1 = __shfl_sync(0xffffffffu, xs, j + 1);
                int a2 = __shfl_sync(0xffffffffu, xs, j + 2);
                int a3 = __shfl_sync(0xffffffffu, xs, j + 3);
                agg_accum4(acc, emb, a0, a1, a2, a3, lane);
            }
        } else {
            int j = 0;
            for (; j + 4 <= cnt; j += 4) {
                int a0 = __shfl_sync(0xffffffffu, xs, j);
                int a1 = __shfl_sync(0xffffffffu, xs, j + 1);
                int a2 = __shfl_sync(0xffffffffu, xs, j + 2);
                int a3 = __shfl_sync(0xffffffffu, xs, j + 3);
                agg_accum4(acc, emb, a0, a1, a2, a3, lane);
            }
            for (; j < cnt; j++) {
                int a = __shfl_sync(0xffffffffu, xs, j);
                float4 v = emb[(size_t)a * 32 + lane];
                acc.x += v.x; acc.y += v.y; acc.z += v.z; acc.w += v.w;
            }
        }
    }
    ((float4*)g_agg)[(size_t)w * 32 + lane] = acc;
}

// ---- layer-2 aggregation: R6-proven serial-shfl version on h table ----
__global__ void k_aggregate(const float4* __restrict__ hin) {
    int w = (blockIdx.x * blockDim.x + threadIdx.x) >> 5;
    int lane = threadIdx.x & 31;
    if (w >= N_NODES) return;
    int start = g_rowstart[w];
    int end = g_rowstart[w + 1];
    float4 acc = make_float4(0.f, 0.f, 0.f, 0.f);
    for (int e = start; e < end; e += 32) {
        int cnt = min(32, end - e);
        int s = (lane < cnt) ? g_esrc[e + lane] : 0;
        for (int j = 0; j < cnt; j++) {
            int sj = __shfl_sync(0xffffffffu, s, j);
            float4 v = hin[(size_t)sj * 32 + lane];
            acc.x += v.x; acc.y += v.y; acc.z += v.z; acc.w += v.w;
        }
    }
    ((float4*)g_agg)[(size_t)w * 32 + lane] = acc;
}

// ---------------- split FFMA2 GEMMs (R6-proven) ----------------
#define GEMM_TILE 64
#define GEMM_NT   1563  // ceil(100000/64)
#define HGEMM_SMEM ((16384 + GEMM_TILE * 128) * 4)

// O = H @ Wo + b   (root half; overlaps aggregation)
__global__ void __launch_bounds__(256, 1)
k_gemm_root(const float* __restrict__ Wo, const float* __restrict__ bias,
            const float* __restrict__ H, float* __restrict__ O) {
    extern __shared__ float sm[];
    float* sWo = sm;
    float* sH  = sm + 16384;

    int tid = threadIdx.x;
    for (int i = tid; i < 4096; i += 256)
        ((float4*)sWo)[i] = ((const float4*)Wo)[i];

    int c0 = (tid & 15) * 8;
    int r0 = (tid >> 4) * 4;
    ulonglong2 bv01 = *(const ulonglong2*)(bias + c0);
    ulonglong2 bv23 = *(const ulonglong2*)(bias + c0 + 4);

    for (int tile = blockIdx.x; tile < GEMM_NT; tile += gridDim.x) {
        int row0 = tile * GEMM_TILE;
        __syncthreads();
        const float4* gH = (const float4*)(H + (size_t)row0 * 128);
        for (int i = tid; i < GEMM_TILE * 32; i += 256)
            if (row0 + (i >> 5) < N_NODES) ((float4*)sH)[i] = gH[i];
        __syncthreads();

        unsigned long long acc[4][4];
#pragma unroll
        for (int r = 0; r < 4; r++) {
            acc[r][0] = bv01.x; acc[r][1] = bv01.y;
            acc[r][2] = bv23.x; acc[r][3] = bv23.y;
        }
        const float* aH = sH + r0 * 128;
#pragma unroll 1
        for (int kk = 0; kk < 128; kk += 4) {
            float4 hv[4];
#pragma unroll
            for (int r = 0; r < 4; r++)
                hv[r] = *(const float4*)(aH + r * 128 + kk);
#pragma unroll
            for (int j = 0; j < 4; j++) {
                int k = kk + j;
                ulonglong2 wo01 = *(const ulonglong2*)(sWo + k * 128 + c0);
                ulonglong2 wo23 = *(const ulonglong2*)(sWo + k * 128 + c0 + 4);
#pragma unroll
                for (int r = 0; r < 4; r++) {
                    float a2 = (j == 0) ? hv[r].x : (j == 1) ? hv[r].y
                             : (j == 2) ? hv[r].z : hv[r].w;
                    unsigned long long p2 = pk2(a2);
                    fma2(acc[r][0], p2, wo01.x);
                    fma2(acc[r][1], p2, wo01.y);
                    fma2(acc[r][2], p2, wo23.x);
                    fma2(acc[r][3], p2, wo23.y);
                }
            }
        }
#pragma unroll
        for (int r = 0; r < 4; r++) {
            int grow = row0 + r0 + r;
            if (grow < N_NODES) {
                float2 f0 = up2(acc[r][0]);
                float2 f1 = up2(acc[r][1]);
                float2 f2 = up2(acc[r][2]);
                float2 f3 = up2(acc[r][3]);
                float4* dst = (float4*)(O + (size_t)grow * 128 + c0);
                dst[0] = make_float4(f0.x, f0.y, f1.x, f1.y);
                dst[1] = make_float4(f2.x, f2.y, f3.x, f3.y);
            }
        }
    }
}

// O = relu(agg @ Wr + O)
__global__ void __launch_bounds__(256, 1)
k_gemm_agg(const float* __restrict__ Wr, float* __restrict__ O) {
    extern __shared__ float sm[];
    float* sWr = sm;
    float* sA  = sm + 16384;
    const float* A = g_agg;

    int tid = threadIdx.x;
    for (int i = tid; i < 4096; i += 256)
        ((float4*)sWr)[i] = ((const float4*)Wr)[i];

    int c0 = (tid & 15) * 8;
    int r0 = (tid >> 4) * 4;

    for (int tile = blockIdx.x; tile < GEMM_NT; tile += gridDim.x) {
        int row0 = tile * GEMM_TILE;
        __syncthreads();
        const float4* gA = (const float4*)(A + (size_t)row0 * 128);
        for (int i = tid; i < GEMM_TILE * 32; i += 256)
            if (row0 + (i >> 5) < N_NODES) ((float4*)sA)[i] = gA[i];
        __syncthreads();

        unsigned long long acc[4][4];
#pragma unroll
        for (int r = 0; r < 4; r++) {
            int grow = row0 + r0 + r;
            if (grow < N_NODES) {
                const float4* po = (const float4*)(O + (size_t)grow * 128 + c0);
                float4 p0 = po[0], p1 = po[1];
                unsigned long long u;
                asm("mov.b64 %0, {%1, %2};" : "=l"(u) : "f"(p0.x), "f"(p0.y)); acc[r][0] = u;
                asm("mov.b64 %0, {%1, %2};" : "=l"(u) : "f"(p0.z), "f"(p0.w)); acc[r][1] = u;
                asm("mov.b64 %0, {%1, %2};" : "=l"(u) : "f"(p1.x), "f"(p1.y)); acc[r][2] = u;
                asm("mov.b64 %0, {%1, %2};" : "=l"(u) : "f"(p1.z), "f"(p1.w)); acc[r][3] = u;
            } else {
                acc[r][0] = acc[r][1] = acc[r][2] = acc[r][3] = 0ull;
            }
        }
        const float* aA = sA + r0 * 128;
#pragma unroll 1
        for (int kk = 0; kk < 128; kk += 4) {
            float4 av[4];
#pragma unroll
            for (int r = 0; r < 4; r++)
                av[r] = *(const float4*)(aA + r * 128 + kk);
#pragma unroll
            for (int j = 0; j < 4; j++) {
                int k = kk + j;
                ulonglong2 wr01 = *(const ulonglong2*)(sWr + k * 128 + c0);
                ulonglong2 wr23 = *(const ulonglong2*)(sWr + k * 128 + c0 + 4);
#pragma unroll
                for (int r = 0; r < 4; r++) {
                    float a1 = (j == 0) ? av[r].x : (j == 1) ? av[r].y
                             : (j == 2) ? av[r].z : av[r].w;
                    unsigned long long p1 = pk2(a1);
                    fma2(acc[r][0], p1, wr01.x);
                    fma2(acc[r][1], p1, wr01.y);
                    fma2(acc[r][2], p1, wr23.x);
                    fma2(acc[r][3], p1, wr23.y);
                }
            }
        }
#pragma unroll
        for (int r = 0; r < 4; r++) {
            int grow = row0 + r0 + r;
            if (grow < N_NODES) {
                float2 f0 = up2(acc[r][0]);
                float2 f1 = up2(acc[r][1]);
                float2 f2 = up2(acc[r][2]);
                float2 f3 = up2(acc[r][3]);
                float4 o0, o1;
                o0.x = fmaxf(f0.x, 0.f); o0.y = fmaxf(f0.y, 0.f);
                o0.z = fmaxf(f1.x, 0.f); o0.w = fmaxf(f1.y, 0.f);
                o1.x = fmaxf(f2.x, 0.f); o1.y = fmaxf(f2.y, 0.f);
                o1.z = fmaxf(f3.x, 0.f); o1.w = fmaxf(f3.y, 0.f);
                float4* dst = (float4*)(O + (size_t)grow * 128 + c0);
                dst[0] = o0;
                dst[1] = o1;
            }
        }
    }
}

// ---------------- pooling ----------------
__device__ __forceinline__ void pool_flush(int gph, int lane, float4 mx, float4 sm) {
    int base = gph * FDIM + lane * 4;
    atomicMax(&g_gmax[base + 0], __float_as_int(mx.x));
    atomicMax(&g_gmax[base + 1], __float_as_int(mx.y));
    atomicMax(&g_gmax[base + 2], __float_as_int(mx.z));
    atomicMax(&g_gmax[base + 3], __float_as_int(mx.w));
    atomicAdd(&g_gsum[base + 0], sm.x);
    atomicAdd(&g_gsum[base + 1], sm.y);
    atomicAdd(&g_gsum[base + 2], sm.z);
    atomicAdd(&g_gsum[base + 3], sm.w);
}

__global__ void k_pool(const int* __restrict__ batch) {
    const float4* __restrict__ h = (const float4*)g_h0;  // layer-2 output
    int w = (blockIdx.x * blockDim.x + threadIdx.x) >> 5;
    int lane = threadIdx.x & 31;
    if (w >= N_NODES / 32) return;
    int n0 = w * 32;
    int cur = batch[n0];
    float4 mx = make_float4(0.f, 0.f, 0.f, 0.f);
    float4 sm = make_float4(0.f, 0.f, 0.f, 0.f);
    for (int i = 0; i < 32; i++) {
        int n = n0 + i;
        int b = batch[n];
        if (b != cur) {
            pool_flush(cur, lane, mx, sm);
            mx = make_float4(0.f, 0.f, 0.f, 0.f);
            sm = make_float4(0.f, 0.f, 0.f, 0.f);
            cur = b;
        }
        float4 v = h[(size_t)n * 32 + lane];
        mx.x = fmaxf(mx.x, v.x); mx.y = fmaxf(mx.y, v.y);
        mx.z = fmaxf(mx.z, v.z); mx.w = fmaxf(mx.w, v.w);
        sm.x += v.x; sm.y += v.y; sm.z += v.z; sm.w += v.w;
    }
    pool_flush(cur, lane, mx, sm);
}

// ---------------- head: one block per graph, then softmax ----------------
__global__ void k_headz(const int* __restrict__ batch,
                        const float* __restrict__ lw1, const float* __restrict__ lb1,
                        const float* __restrict__ lw2, const float* __restrict__ lb2,
                        const float* __restrict__ lw3, const float* __restrict__ lb3) {
    __shared__ float m1[128];
    __shared__ float m2[64];
    __shared__ int bnd[2];
    int g = blockIdx.x;
    int tid = threadIdx.x;

    if (tid < 2) {
        int target = g + tid;
        int lo = 0, hi = N_NODES;
        while (lo < hi) {
            int mid = (lo + hi) >> 1;
            if (batch[mid] < target) lo = mid + 1; else hi = mid;
        }
        bnd[tid] = lo;
    }
    __syncthreads();

    {
        int cnt = bnd[1] - bnd[0];
        float inv = 1.0f / (float)(cnt > 1 ? cnt : 1);
        int c = tid;
        float acc = lb1[c];
#pragma unroll 4
        for (int k = 0; k < 128; k++)
            acc += __int_as_float(g_gmax[g * 128 + k]) * lw1[k * 128 + c];
#pragma unroll 4
        for (int k = 0; k < 128; k++)
            acc += (g_gsum[g * 128 + k] * inv) * lw1[(128 + k) * 128 + c];
        m1[c] = fmaxf(acc, 0.f);
    }
    __syncthreads();

    if (tid < 64) {
        int c = tid;
        float acc = lb2[c];
#pragma unroll 4
        for (int k = 0; k < 128; k++) acc += m1[k] * lw2[k * 64 + c];
        m2[c] = fmaxf(acc, 0.f);
    }
    __syncthreads();

    if (tid < NL) {
        int l = tid;
        float acc = lb3[l];
#pragma unroll 4
        for (int k = 0; k < 64; k++) acc += m2[k] * lw3[k * NL + l];
        g_z[g * NL + l] = acc;
    }
}

__global__ void k_softmax(float* __restrict__ out) {
    int l = threadIdx.x;
    if (l >= NL) return;
    float m = -1e30f;
    for (int g = 0; g < NG; g++) m = fmaxf(m, g_z[g * NL + l]);
    float s = 0.f;
    for (int g = 0; g < NG; g++) s += expf(g_z[g * NL + l] - m);
    float ls = m + logf(s);
    for (int g = 0; g < NG; g++) out[g * NL + l] = g_z[g * NL + l] - ls;
}

// ---------------- launch ----------------
extern "C" void kernel_launch(void* const* d_in, const int* in_sizes, int n_in,
                              void* d_out, int out_size) {
    const int*   x       = (const int*)d_in[0];
    const int*   ei      = (const int*)d_in[1];
    const int*   batch   = (const int*)d_in[2];
    const float* emb     = (const float*)d_in[3];
    const float* w1_rel  = (const float*)d_in[4];
    const float* w1_root = (const float*)d_in[5];
    const float* b1      = (const float*)d_in[6];
    const float* w2_rel  = (const float*)d_in[7];
    const float* w2_root = (const float*)d_in[8];
    const float* b2      = (const float*)d_in[9];
    const float* lw1     = (const float*)d_in[10];
    const float* lb1     = (const float*)d_in[11];
    const float* lw2     = (const float*)d_in[12];
    const float* lb2     = (const float*)d_in[13];
    const float* lw3     = (const float*)d_in[14];
    const float* lb3     = (const float*)d_in[15];
    const int* src = ei;
    const int* dst = ei + N_EDGES;
    float* out = (float*)d_out;

    float *h0, *h1;
    void *p_deg, *p_bsum, *p_gmax, *p_gsum;
    cudaGetSymbolAddress((void**)&h0, g_h0);
    cudaGetSymbolAddress((void**)&h1, g_h1);
    cudaGetSymbolAddress(&p_deg, g_deg);
    cudaGetSymbolAddress(&p_bsum, g_blocksums);
    cudaGetSymbolAddress(&p_gmax, g_gmax);
    cudaGetSymbolAddress(&p_gsum, g_gsum);

    cudaFuncSetAttribute(k_gemm_root, cudaFuncAttributeMaxDynamicSharedMemorySize, HGEMM_SMEM);
    cudaFuncSetAttribute(k_gemm_agg, cudaFuncAttributeMaxDynamicSharedMemorySize, HGEMM_SMEM);

    cudaStream_t s2;
    cudaStreamCreateWithFlags(&s2, cudaStreamNonBlocking);
    cudaEvent_t ev[4];
    for (int i = 0; i < 4; i++) cudaEventCreateWithFlags(&ev[i], cudaEventDisableTiming);

    cudaMemsetAsync(p_deg, 0, N_NODES * sizeof(int));
    cudaMemsetAsync(p_bsum, 0, 512 * sizeof(int));
    cudaMemsetAsync(p_gmax, 0, NG * FDIM * sizeof(int));
    cudaMemsetAsync(p_gsum, 0, NG * FDIM * sizeof(float));
    cudaEventRecord(ev[0], 0);

    // s2 (overlaps CSR + agg_emb): h0 = emb[x]; h1 = h0 @ Wo1 + b1
    cudaStreamWaitEvent(s2, ev[0], 0);
    k_gather<<<12500, 256, 0, s2>>>(x, (const float4*)emb);
    k_gemm_root<<<148, 256, HGEMM_SMEM, s2>>>(w1_root, b1, h0, h1);
    cudaEventRecord(ev[1], s2);

    // stream 0: CSR build, then layer-1 aggregation straight from emb
    k_count<<<N_EDGES / 256, 256>>>(dst);
    k_scan23<<<SCAN_NB, 256>>>();
    k_fill<<<N_EDGES / 256, 256>>>(src, dst);
    k_agg_emb<<<12500, 256>>>(x, (const float4*)emb);

    // join: h1 = relu(agg @ Wr1 + h1)
    cudaStreamWaitEvent(0, ev[1], 0);
    k_gemm_agg<<<148, 256, HGEMM_SMEM>>>(w1_rel, h1);
    cudaEventRecord(ev[2], 0);

    // layer 2: root2 on s2 (h0 = h1 @ Wo2 + b2) || aggregate(h1) on 0
    cudaStreamWaitEvent(s2, ev[2], 0);
    k_gemm_root<<<148, 256, HGEMM_SMEM, s2>>>(w2_root, b2, h1, h0);
    k_aggregate<<<12500, 256>>>((const float4*)h1);
    cudaEventRecord(ev[3], s2);
    cudaStreamWaitEvent(0, ev[3], 0);
    k_gemm_agg<<<148, 256, HGEMM_SMEM>>>(w2_rel, h0);

    // pooling + head
    k_pool<<<SCAN_NB, 256>>>(batch);
    k_headz<<<NG, 128>>>(batch, lw1, lb1, lw2, lb2, lw3, lb3);
    k_softmax<<<1, 32>>>(out);
}

// round 11
// speedup vs baseline: 1.0520x; 1.0520x over previous
#include <cuda_runtime.h>
#include <math.h>

#define N_NODES 100000
#define N_EDGES 1600000
#define FDIM 128
#define NG 64
#define NL 20
#define SCAN_NB 391   // ceil(100000/256)

// ---------------- device scratch ----------------
__device__ float g_h0[N_NODES * FDIM];
__device__ float g_h1[N_NODES * FDIM];
__device__ float g_agg[N_NODES * FDIM];
__device__ int   g_deg[N_NODES];
__device__ int   g_rowstart[N_NODES + 1];
__device__ int   g_cursor[N_NODES];
__device__ int   g_esrc[N_EDGES];
__device__ int   g_blocksums[512];
__device__ int   g_gmax[NG * FDIM];   // float bits; relu outputs >= 0 so int-max == float-max
__device__ float g_gsum[NG * FDIM];
__device__ float g_z[NG * NL];

// ---------------- f32x2 helpers (FFMA2 path, PTX-only) ----------------
__device__ __forceinline__ unsigned long long pk2(float a) {
    unsigned long long r;
    asm("mov.b64 %0, {%1, %1};" : "=l"(r) : "f"(a));
    return r;
}
__device__ __forceinline__ void fma2(unsigned long long& d, unsigned long long a,
                                     unsigned long long b) {
    asm("fma.rn.f32x2 %0, %1, %2, %0;" : "+l"(d) : "l"(a), "l"(b));
}
__device__ __forceinline__ float2 up2(unsigned long long v) {
    float2 f;
    asm("mov.b64 {%0, %1}, %2;" : "=f"(f.x), "=f"(f.y) : "l"(v));
    return f;
}

// ---------------- CSR build ----------------
// count fused with per-scanblock partial sums (replaces separate scan1)
__global__ void k_count(const int* __restrict__ dst) {
    int e = blockIdx.x * blockDim.x + threadIdx.x;
    if (e < N_EDGES) {
        int d = dst[e];
        atomicAdd(&g_deg[d], 1);
        atomicAdd(&g_blocksums[d >> 8], 1);
    }
}

__device__ __forceinline__ int block_scan_inc(int v, int* warpbuf) {
    int tid = threadIdx.x, lane = tid & 31, wid = tid >> 5;
#pragma unroll
    for (int off = 1; off < 32; off <<= 1) {
        int t = __shfl_up_sync(0xffffffffu, v, off);
        if (lane >= off) v += t;
    }
    if (lane == 31) warpbuf[wid] = v;
    __syncthreads();
    if (wid == 0) {
        int nw = blockDim.x >> 5;
        int w = (lane < nw) ? warpbuf[lane] : 0;
#pragma unroll
        for (int off = 1; off < 32; off <<= 1) {
            int t = __shfl_up_sync(0xffffffffu, w, off);
            if (lane >= off) w += t;
        }
        warpbuf[lane] = w;
    }
    __syncthreads();
    return v + (wid > 0 ? warpbuf[wid - 1] : 0);
}

__global__ void k_scan23() {
    __shared__ int wb[32];
    __shared__ int s_off;
    int tid = threadIdx.x;
    int i = blockIdx.x * blockDim.x + tid;
    int v = (i < N_NODES) ? g_deg[i] : 0;
    int inc = block_scan_inc(v, wb);
    if (tid < 32) {
        int p = 0;
        for (int j = tid; j < blockIdx.x; j += 32) p += g_blocksums[j];
#pragma unroll
        for (int off = 16; off > 0; off >>= 1)
            p += __shfl_down_sync(0xffffffffu, p, off);
        if (tid == 0) s_off = p;
    }
    __syncthreads();
    if (i < N_NODES) {
        int ex = s_off + inc - v;
        g_rowstart[i] = ex;
        g_cursor[i] = ex;
        if (i == N_NODES - 1) g_rowstart[N_NODES] = ex + v;
    }
}

__global__ void k_fill(const int* __restrict__ src, const int* __restrict__ dst) {
    int e = blockIdx.x * blockDim.x + threadIdx.x;
    if (e >= N_EDGES) return;
    int d = dst[e];
    int pos = atomicAdd(&g_cursor[d], 1);
    g_esrc[pos] = src[e];
}

// ---------------- embedding gather (s2; concurrent with CSR) ----------------
__global__ void k_gather(const int* __restrict__ x, const float4* __restrict__ emb) {
    int idx = blockIdx.x * blockDim.x + threadIdx.x;
    if (idx >= N_NODES * 32) return;
    int node = idx >> 5;
    int c = idx & 31;
    ((float4*)g_h0)[idx] = emb[(size_t)x[node] * 32 + c];
}

// ---- aggregation: warp per node, MLP=4 pipelined rows via unrolled shfl ----
// runs concurrent with gemm_root which READS THE SAME hin table (cooperative L2)
__device__ __forceinline__ void agg_accum4(float4& acc, const float4* __restrict__ tab,
                                           int a0, int a1, int a2, int a3, int lane) {
    float4 v0 = tab[(size_t)a0 * 32 + lane];
    float4 v1 = tab[(size_t)a1 * 32 + lane];
    float4 v2 = tab[(size_t)a2 * 32 + lane];
    float4 v3 = tab[(size_t)a3 * 32 + lane];
    acc.x += (v0.x + v1.x) + (v2.x + v3.x);
    acc.y += (v0.y + v1.y) + (v2.y + v3.y);
    acc.z += (v0.z + v1.z) + (v2.z + v3.z);
    acc.w += (v0.w + v1.w) + (v2.w + v3.w);
}

__global__ void k_aggregate(const float4* __restrict__ hin) {
    int w = (blockIdx.x * blockDim.x + threadIdx.x) >> 5;
    int lane = threadIdx.x & 31;
    if (w >= N_NODES) return;
    int s = g_rowstart[w], e = g_rowstart[w + 1];
    float4 acc = make_float4(0.f, 0.f, 0.f, 0.f);
    for (int i = s; i < e; i += 32) {
        int cnt = min(32, e - i);
        int xs = g_esrc[i + ((lane < cnt) ? lane : 0)];
        if (cnt == 32) {
#pragma unroll
            for (int j = 0; j < 32; j += 4) {
                int a0 = __shfl_sync(0xffffffffu, xs, j);
                int a1 = __shfl_sync(0xffffffffu, xs, j + 1);
                int a2 = __shfl_sync(0xffffffffu, xs, j + 2);
                int a3 = __shfl_sync(0xffffffffu, xs, j + 3);
                agg_accum4(acc, hin, a0, a1, a2, a3, lane);
            }
        } else {
            int j = 0;
            for (; j + 4 <= cnt; j += 4) {
                int a0 = __shfl_sync(0xffffffffu, xs, j);
                int a1 = __shfl_sync(0xffffffffu, xs, j + 1);
                int a2 = __shfl_sync(0xffffffffu, xs, j + 2);
                int a3 = __shfl_sync(0xffffffffu, xs, j + 3);
                agg_accum4(acc, hin, a0, a1, a2, a3, lane);
            }
            for (; j < cnt; j++) {
                int a = __shfl_sync(0xffffffffu, xs, j);
                float4 v = hin[(size_t)a * 32 + lane];
                acc.x += v.x; acc.y += v.y; acc.z += v.z; acc.w += v.w;
            }
        }
    }
    ((float4*)g_agg)[(size_t)w * 32 + lane] = acc;
}

// ---------------- split FFMA2 GEMMs (R6-proven) ----------------
#define GEMM_TILE 64
#define GEMM_NT   1563  // ceil(100000/64)
#define HGEMM_SMEM ((16384 + GEMM_TILE * 128) * 4)

// O = H @ Wo + b   (root half; overlaps aggregation reading the same H)
__global__ void __launch_bounds__(256, 1)
k_gemm_root(const float* __restrict__ Wo, const float* __restrict__ bias,
            const float* __restrict__ H, float* __restrict__ O) {
    extern __shared__ float sm[];
    float* sWo = sm;
    float* sH  = sm + 16384;

    int tid = threadIdx.x;
    for (int i = tid; i < 4096; i += 256)
        ((float4*)sWo)[i] = ((const float4*)Wo)[i];

    int c0 = (tid & 15) * 8;
    int r0 = (tid >> 4) * 4;
    ulonglong2 bv01 = *(const ulonglong2*)(bias + c0);
    ulonglong2 bv23 = *(const ulonglong2*)(bias + c0 + 4);

    for (int tile = blockIdx.x; tile < GEMM_NT; tile += gridDim.x) {
        int row0 = tile * GEMM_TILE;
        __syncthreads();
        const float4* gH = (const float4*)(H + (size_t)row0 * 128);
        for (int i = tid; i < GEMM_TILE * 32; i += 256)
            if (row0 + (i >> 5) < N_NODES) ((float4*)sH)[i] = gH[i];
        __syncthreads();

        unsigned long long acc[4][4];
#pragma unroll
        for (int r = 0; r < 4; r++) {
            acc[r][0] = bv01.x; acc[r][1] = bv01.y;
            acc[r][2] = bv23.x; acc[r][3] = bv23.y;
        }
        const float* aH = sH + r0 * 128;
#pragma unroll 1
        for (int kk = 0; kk < 128; kk += 4) {
            float4 hv[4];
#pragma unroll
            for (int r = 0; r < 4; r++)
                hv[r] = *(const float4*)(aH + r * 128 + kk);
#pragma unroll
            for (int j = 0; j < 4; j++) {
                int k = kk + j;
                ulonglong2 wo01 = *(const ulonglong2*)(sWo + k * 128 + c0);
                ulonglong2 wo23 = *(const ulonglong2*)(sWo + k * 128 + c0 + 4);
#pragma unroll
                for (int r = 0; r < 4; r++) {
                    float a2 = (j == 0) ? hv[r].x : (j == 1) ? hv[r].y
                             : (j == 2) ? hv[r].z : hv[r].w;
                    unsigned long long p2 = pk2(a2);
                    fma2(acc[r][0], p2, wo01.x);
                    fma2(acc[r][1], p2, wo01.y);
                    fma2(acc[r][2], p2, wo23.x);
                    fma2(acc[r][3], p2, wo23.y);
                }
            }
        }
#pragma unroll
        for (int r = 0; r < 4; r++) {
            int grow = row0 + r0 + r;
            if (grow < N_NODES) {
                float2 f0 = up2(acc[r][0]);
                float2 f1 = up2(acc[r][1]);
                float2 f2 = up2(acc[r][2]);
                float2 f3 = up2(acc[r][3]);
                float4* dst = (float4*)(O + (size_t)grow * 128 + c0);
                dst[0] = make_float4(f0.x, f0.y, f1.x, f1.y);
                dst[1] = make_float4(f2.x, f2.y, f3.x, f3.y);
            }
        }
    }
}

// O = relu(agg @ Wr + O)
__global__ void __launch_bounds__(256, 1)
k_gemm_agg(const float* __restrict__ Wr, float* __restrict__ O) {
    extern __shared__ float sm[];
    float* sWr = sm;
    float* sA  = sm + 16384;
    const float* A = g_agg;

    int tid = threadIdx.x;
    for (int i = tid; i < 4096; i += 256)
        ((float4*)sWr)[i] = ((const float4*)Wr)[i];

    int c0 = (tid & 15) * 8;
    int r0 = (tid >> 4) * 4;

    for (int tile = blockIdx.x; tile < GEMM_NT; tile += gridDim.x) {
        int row0 = tile * GEMM_TILE;
        __syncthreads();
        const float4* gA = (const float4*)(A + (size_t)row0 * 128);
        for (int i = tid; i < GEMM_TILE * 32; i += 256)
            if (row0 + (i >> 5) < N_NODES) ((float4*)sA)[i] = gA[i];
        __syncthreads();

        unsigned long long acc[4][4];
#pragma unroll
        for (int r = 0; r < 4; r++) {
            int grow = row0 + r0 + r;
            if (grow < N_NODES) {
                const float4* po = (const float4*)(O + (size_t)grow * 128 + c0);
                float4 p0 = po[0], p1 = po[1];
                unsigned long long u;
                asm("mov.b64 %0, {%1, %2};" : "=l"(u) : "f"(p0.x), "f"(p0.y)); acc[r][0] = u;
                asm("mov.b64 %0, {%1, %2};" : "=l"(u) : "f"(p0.z), "f"(p0.w)); acc[r][1] = u;
                asm("mov.b64 %0, {%1, %2};" : "=l"(u) : "f"(p1.x), "f"(p1.y)); acc[r][2] = u;
                asm("mov.b64 %0, {%1, %2};" : "=l"(u) : "f"(p1.z), "f"(p1.w)); acc[r][3] = u;
            } else {
                acc[r][0] = acc[r][1] = acc[r][2] = acc[r][3] = 0ull;
            }
        }
        const float* aA = sA + r0 * 128;
#pragma unroll 1
        for (int kk = 0; kk < 128; kk += 4) {
            float4 av[4];
#pragma unroll
            for (int r = 0; r < 4; r++)
                av[r] = *(const float4*)(aA + r * 128 + kk);
#pragma unroll
            for (int j = 0; j < 4; j++) {
                int k = kk + j;
                ulonglong2 wr01 = *(const ulonglong2*)(sWr + k * 128 + c0);
                ulonglong2 wr23 = *(const ulonglong2*)(sWr + k * 128 + c0 + 4);
#pragma unroll
                for (int r = 0; r < 4; r++) {
                    float a1 = (j == 0) ? av[r].x : (j == 1) ? av[r].y
                             : (j == 2) ? av[r].z : av[r].w;
                    unsigned long long p1 = pk2(a1);
                    fma2(acc[r][0], p1, wr01.x);
                    fma2(acc[r][1], p1, wr01.y);
                    fma2(acc[r][2], p1, wr23.x);
                    fma2(acc[r][3], p1, wr23.y);
                }
            }
        }
#pragma unroll
        for (int r = 0; r < 4; r++) {
            int grow = row0 + r0 + r;
            if (grow < N_NODES) {
                float2 f0 = up2(acc[r][0]);
                float2 f1 = up2(acc[r][1]);
                float2 f2 = up2(acc[r][2]);
                float2 f3 = up2(acc[r][3]);
                float4 o0, o1;
                o0.x = fmaxf(f0.x, 0.f); o0.y = fmaxf(f0.y, 0.f);
                o0.z = fmaxf(f1.x, 0.f); o0.w = fmaxf(f1.y, 0.f);
                o1.x = fmaxf(f2.x, 0.f); o1.y = fmaxf(f2.y, 0.f);
                o1.z = fmaxf(f3.x, 0.f); o1.w = fmaxf(f3.y, 0.f);
                float4* dst = (float4*)(O + (size_t)grow * 128 + c0);
                dst[0] = o0;
                dst[1] = o1;
            }
        }
    }
}

// ---------------- pooling ----------------
__device__ __forceinline__ void pool_flush(int gph, int lane, float4 mx, float4 sm) {
    int base = gph * FDIM + lane * 4;
    atomicMax(&g_gmax[base + 0], __float_as_int(mx.x));
    atomicMax(&g_gmax[base + 1], __float_as_int(mx.y));
    atomicMax(&g_gmax[base + 2], __float_as_int(mx.z));
    atomicMax(&g_gmax[base + 3], __float_as_int(mx.w));
    atomicAdd(&g_gsum[base + 0], sm.x);
    atomicAdd(&g_gsum[base + 1], sm.y);
    atomicAdd(&g_gsum[base + 2], sm.z);
    atomicAdd(&g_gsum[base + 3], sm.w);
}

__global__ void k_pool(const int* __restrict__ batch) {
    const float4* __restrict__ h = (const float4*)g_h0;  // layer-2 output
    int w = (blockIdx.x * blockDim.x + threadIdx.x) >> 5;
    int lane = threadIdx.x & 31;
    if (w >= N_NODES / 32) return;
    int n0 = w * 32;
    int cur = batch[n0];
    float4 mx = make_float4(0.f, 0.f, 0.f, 0.f);
    float4 sm = make_float4(0.f, 0.f, 0.f, 0.f);
    for (int i = 0; i < 32; i++) {
        int n = n0 + i;
        int b = batch[n];
        if (b != cur) {
            pool_flush(cur, lane, mx, sm);
            mx = make_float4(0.f, 0.f, 0.f, 0.f);
            sm = make_float4(0.f, 0.f, 0.f, 0.f);
            cur = b;
        }
        float4 v = h[(size_t)n * 32 + lane];
        mx.x = fmaxf(mx.x, v.x); mx.y = fmaxf(mx.y, v.y);
        mx.z = fmaxf(mx.z, v.z); mx.w = fmaxf(mx.w, v.w);
        sm.x += v.x; sm.y += v.y; sm.z += v.z; sm.w += v.w;
    }
    pool_flush(cur, lane, mx, sm);
}

// ---------------- head: one block per graph, then softmax ----------------
__global__ void k_headz(const int* __restrict__ batch,
                        const float* __restrict__ lw1, const float* __restrict__ lb1,
                        const float* __restrict__ lw2, const float* __restrict__ lb2,
                        const float* __restrict__ lw3, const float* __restrict__ lb3) {
    __shared__ float m1[128];
    __shared__ float m2[64];
    __shared__ int bnd[2];
    int g = blockIdx.x;
    int tid = threadIdx.x;

    if (tid < 2) {
        int target = g + tid;
        int lo = 0, hi = N_NODES;
        while (lo < hi) {
            int mid = (lo + hi) >> 1;
            if (batch[mid] < target) lo = mid + 1; else hi = mid;
        }
        bnd[tid] = lo;
    }
    __syncthreads();

    {
        int cnt = bnd[1] - bnd[0];
        float inv = 1.0f / (float)(cnt > 1 ? cnt : 1);
        int c = tid;
        float acc = lb1[c];
#pragma unroll 4
        for (int k = 0; k < 128; k++)
            acc += __int_as_float(g_gmax[g * 128 + k]) * lw1[k * 128 + c];
#pragma unroll 4
        for (int k = 0; k < 128; k++)
            acc += (g_gsum[g * 128 + k] * inv) * lw1[(128 + k) * 128 + c];
        m1[c] = fmaxf(acc, 0.f);
    }
    __syncthreads();

    if (tid < 64) {
        int c = tid;
        float acc = lb2[c];
#pragma unroll 4
        for (int k = 0; k < 128; k++) acc += m1[k] * lw2[k * 64 + c];
        m2[c] = fmaxf(acc, 0.f);
    }
    __syncthreads();

    if (tid < NL) {
        int l = tid;
        float acc = lb3[l];
#pragma unroll 4
        for (int k = 0; k < 64; k++) acc += m2[k] * lw3[k * NL + l];
        g_z[g * NL + l] = acc;
    }
}

__global__ void k_softmax(float* __restrict__ out) {
    int l = threadIdx.x;
    if (l >= NL) return;
    float m = -1e30f;
    for (int g = 0; g < NG; g++) m = fmaxf(m, g_z[g * NL + l]);
    float s = 0.f;
    for (int g = 0; g < NG; g++) s += expf(g_z[g * NL + l] - m);
    float ls = m + logf(s);
    for (int g = 0; g < NG; g++) out[g * NL + l] = g_z[g * NL + l] - ls;
}

// ---------------- launch (R6 topology verbatim) ----------------
extern "C" void kernel_launch(void* const* d_in, const int* in_sizes, int n_in,
                              void* d_out, int out_size) {
    const int*   x       = (const int*)d_in[0];
    const int*   ei      = (const int*)d_in[1];
    const int*   batch   = (const int*)d_in[2];
    const float* emb     = (const float*)d_in[3];
    const float* w1_rel  = (const float*)d_in[4];
    const float* w1_root = (const float*)d_in[5];
    const float* b1      = (const float*)d_in[6];
    const float* w2_rel  = (const float*)d_in[7];
    const float* w2_root = (const float*)d_in[8];
    const float* b2      = (const float*)d_in[9];
    const float* lw1     = (const float*)d_in[10];
    const float* lb1     = (const float*)d_in[11];
    const float* lw2     = (const float*)d_in[12];
    const float* lb2     = (const float*)d_in[13];
    const float* lw3     = (const float*)d_in[14];
    const float* lb3     = (const float*)d_in[15];
    const int* src = ei;
    const int* dst = ei + N_EDGES;
    float* out = (float*)d_out;

    float *h0, *h1;
    void *p_deg, *p_bsum, *p_gmax, *p_gsum;
    cudaGetSymbolAddress((void**)&h0, g_h0);
    cudaGetSymbolAddress((void**)&h1, g_h1);
    cudaGetSymbolAddress(&p_deg, g_deg);
    cudaGetSymbolAddress(&p_bsum, g_blocksums);
    cudaGetSymbolAddress(&p_gmax, g_gmax);
    cudaGetSymbolAddress(&p_gsum, g_gsum);

    cudaFuncSetAttribute(k_gemm_root, cudaFuncAttributeMaxDynamicSharedMemorySize, HGEMM_SMEM);
    cudaFuncSetAttribute(k_gemm_agg, cudaFuncAttributeMaxDynamicSharedMemorySize, HGEMM_SMEM);

    cudaStream_t s2;
    cudaStreamCreateWithFlags(&s2, cudaStreamNonBlocking);
    cudaEvent_t ev[6];
    for (int i = 0; i < 6; i++) cudaEventCreateWithFlags(&ev[i], cudaEventDisableTiming);

    cudaMemsetAsync(p_deg, 0, N_NODES * sizeof(int));
    cudaMemsetAsync(p_bsum, 0, 512 * sizeof(int));
    cudaMemsetAsync(p_gmax, 0, NG * FDIM * sizeof(int));
    cudaMemsetAsync(p_gsum, 0, NG * FDIM * sizeof(float));

    // fork: gather on s2, CSR chain on default stream (R6 pattern)
    cudaEventRecord(ev[0], 0);
    cudaStreamWaitEvent(s2, ev[0], 0);
    k_gather<<<12500, 256, 0, s2>>>(x, (const float4*)emb);

    k_count<<<N_EDGES / 256, 256>>>(dst);
    k_scan23<<<SCAN_NB, 256>>>();
    k_fill<<<N_EDGES / 256, 256>>>(src, dst);

    cudaEventRecord(ev[1], s2);
    cudaStreamWaitEvent(0, ev[1], 0);

    // ---- layer 1: aggregate(h0) || gemm_root(h0@Wo) — shared h0 working set ----
    cudaEventRecord(ev[2], 0);
    cudaStreamWaitEvent(s2, ev[2], 0);
    k_gemm_root<<<148, 256, HGEMM_SMEM, s2>>>(w1_root, b1, h0, h1);
    k_aggregate<<<12500, 256>>>((const float4*)h0);
    cudaEventRecord(ev[3], s2);
    cudaStreamWaitEvent(0, ev[3], 0);
    k_gemm_agg<<<148, 256, HGEMM_SMEM>>>(w1_rel, h1);

    // ---- layer 2 ----
    cudaEventRecord(ev[4], 0);
    cudaStreamWaitEvent(s2, ev[4], 0);
    k_gemm_root<<<148, 256, HGEMM_SMEM, s2>>>(w2_root, b2, h1, h0);
    k_aggregate<<<12500, 256>>>((const float4*)h1);
    cudaEventRecord(ev[5], s2);
    cudaStreamWaitEvent(0, ev[5], 0);
    k_gemm_agg<<<148, 256, HGEMM_SMEM>>>(w2_rel, h0);

    // pooling + head
    k_pool<<<SCAN_NB, 256>>>(batch);
    k_headz<<<NG, 128>>>(batch, lw1, lb1, lw2, lb2, lw3, lb3);
    k_softmax<<<1, 32>>>(out);
}

// round 12
// speedup vs baseline: 1.4336x; 1.3627x over previous
#include <cuda_runtime.h>
#include <cuda_fp16.h>
#include <math.h>

#define N_NODES 100000
#define N_EDGES 1600000
#define FDIM 128
#define NG 64
#define NL 20
#define SCAN_NB 391   // ceil(100000/256)

// ---------------- device scratch ----------------
__device__ float  g_h0[N_NODES * FDIM];
__device__ float  g_h1[N_NODES * FDIM];
__device__ __half g_h0h[N_NODES * FDIM];   // fp16 mirror for gather
__device__ __half g_h1h[N_NODES * FDIM];   // fp16 mirror for gather
__device__ float  g_agg[N_NODES * FDIM];
__device__ int    g_deg[N_NODES];
__device__ int    g_rowstart[N_NODES + 1];
__device__ int    g_cursor[N_NODES];
__device__ int    g_esrc[N_EDGES];
__device__ int    g_blocksums[512];
__device__ int    g_gmax[NG * FDIM];  // float bits; relu outputs >= 0
__device__ float  g_gsum[NG * FDIM];
__device__ float  g_z[NG * NL];

// ---------------- f32x2 helpers (FFMA2 path, PTX-only) ----------------
__device__ __forceinline__ unsigned long long pk2(float a) {
    unsigned long long r;
    asm("mov.b64 %0, {%1, %1};" : "=l"(r) : "f"(a));
    return r;
}
__device__ __forceinline__ void fma2(unsigned long long& d, unsigned long long a,
                                     unsigned long long b) {
    asm("fma.rn.f32x2 %0, %1, %2, %0;" : "+l"(d) : "l"(a), "l"(b));
}
__device__ __forceinline__ float2 up2(unsigned long long v) {
    float2 f;
    asm("mov.b64 {%0, %1}, %2;" : "=f"(f.x), "=f"(f.y) : "l"(v));
    return f;
}

// ---------------- CSR build (R6 exact: NO hot-counter atomics) ----------------
__global__ void k_count(const int* __restrict__ dst) {
    int e = blockIdx.x * blockDim.x + threadIdx.x;
    if (e < N_EDGES) atomicAdd(&g_deg[dst[e]], 1);
}

__device__ __forceinline__ int block_scan_inc(int v, int* warpbuf) {
    int tid = threadIdx.x, lane = tid & 31, wid = tid >> 5;
#pragma unroll
    for (int off = 1; off < 32; off <<= 1) {
        int t = __shfl_up_sync(0xffffffffu, v, off);
        if (lane >= off) v += t;
    }
    if (lane == 31) warpbuf[wid] = v;
    __syncthreads();
    if (wid == 0) {
        int nw = blockDim.x >> 5;
        int w = (lane < nw) ? warpbuf[lane] : 0;
#pragma unroll
        for (int off = 1; off < 32; off <<= 1) {
            int t = __shfl_up_sync(0xffffffffu, w, off);
            if (lane >= off) w += t;
        }
        warpbuf[lane] = w;
    }
    __syncthreads();
    return v + (wid > 0 ? warpbuf[wid - 1] : 0);
}

__global__ void k_scan1() {
    __shared__ int wb[32];
    int i = blockIdx.x * blockDim.x + threadIdx.x;
    int v = (i < N_NODES) ? g_deg[i] : 0;
    int inc = block_scan_inc(v, wb);
    if (threadIdx.x == blockDim.x - 1) g_blocksums[blockIdx.x] = inc;
}

__global__ void k_scan23() {
    __shared__ int wb[32];
    __shared__ int s_off;
    int tid = threadIdx.x;
    int i = blockIdx.x * blockDim.x + tid;
    int v = (i < N_NODES) ? g_deg[i] : 0;
    int inc = block_scan_inc(v, wb);
    if (tid < 32) {
        int p = 0;
        for (int j = tid; j < blockIdx.x; j += 32) p += g_blocksums[j];
#pragma unroll
        for (int off = 16; off > 0; off >>= 1)
            p += __shfl_down_sync(0xffffffffu, p, off);
        if (tid == 0) s_off = p;
    }
    __syncthreads();
    if (i < N_NODES) {
        int ex = s_off + inc - v;
        g_rowstart[i] = ex;
        g_cursor[i] = ex;
        if (i == N_NODES - 1) g_rowstart[N_NODES] = ex + v;
    }
}

__global__ void k_fill(const int* __restrict__ src, const int* __restrict__ dst) {
    int e = blockIdx.x * blockDim.x + threadIdx.x;
    if (e >= N_EDGES) return;
    int d = dst[e];
    int pos = atomicAdd(&g_cursor[d], 1);
    g_esrc[pos] = src[e];
}

// ---------------- embedding gather: fp32 + fp16 mirror ----------------
__global__ void k_gather(const int* __restrict__ x, const float4* __restrict__ emb) {
    int idx = blockIdx.x * blockDim.x + threadIdx.x;
    if (idx >= N_NODES * 32) return;
    int node = idx >> 5;
    int c = idx & 31;
    float4 v = emb[(size_t)x[node] * 32 + c];
    ((float4*)g_h0)[idx] = v;
    __half2 p0 = __floats2half2_rn(v.x, v.y);
    __half2 p1 = __floats2half2_rn(v.z, v.w);
    uint2 u;
    u.x = *(unsigned int*)&p0;
    u.y = *(unsigned int*)&p1;
    ((uint2*)g_h0h)[idx] = u;
}

// ---- aggregation: warp per node, serial-shfl (R6-proven), fp16 input ----
__global__ void k_aggregate(const uint2* __restrict__ hin2) {
    int w = (blockIdx.x * blockDim.x + threadIdx.x) >> 5;
    int lane = threadIdx.x & 31;
    if (w >= N_NODES) return;
    int start = g_rowstart[w];
    int end = g_rowstart[w + 1];
    float4 acc = make_float4(0.f, 0.f, 0.f, 0.f);
    for (int e = start; e < end; e += 32) {
        int cnt = min(32, end - e);
        int s = (lane < cnt) ? g_esrc[e + lane] : 0;
        for (int j = 0; j < cnt; j++) {
            int sj = __shfl_sync(0xffffffffu, s, j);
            uint2 u = hin2[(size_t)sj * 32 + lane];
            __half2 p0 = *(__half2*)&u.x;
            __half2 p1 = *(__half2*)&u.y;
            float2 f0 = __half22float2(p0);
            float2 f1 = __half22float2(p1);
            acc.x += f0.x; acc.y += f0.y; acc.z += f1.x; acc.w += f1.y;
        }
    }
    ((float4*)g_agg)[(size_t)w * 32 + lane] = acc;
}

// ---------------- split FFMA2 GEMMs (R6-proven) ----------------
#define GEMM_TILE 64
#define GEMM_NT   1563  // ceil(100000/64)
#define HGEMM_SMEM ((16384 + GEMM_TILE * 128) * 4)

// O = H @ Wo + b   (root half; overlaps aggregation reading the same layer)
__global__ void __launch_bounds__(256, 1)
k_gemm_root(const float* __restrict__ Wo, const float* __restrict__ bias,
            const float* __restrict__ H, float* __restrict__ O) {
    extern __shared__ float sm[];
    float* sWo = sm;
    float* sH  = sm + 16384;

    int tid = threadIdx.x;
    for (int i = tid; i < 4096; i += 256)
        ((float4*)sWo)[i] = ((const float4*)Wo)[i];

    int c0 = (tid & 15) * 8;
    int r0 = (tid >> 4) * 4;
    ulonglong2 bv01 = *(const ulonglong2*)(bias + c0);
    ulonglong2 bv23 = *(const ulonglong2*)(bias + c0 + 4);

    for (int tile = blockIdx.x; tile < GEMM_NT; tile += gridDim.x) {
        int row0 = tile * GEMM_TILE;
        __syncthreads();
        const float4* gH = (const float4*)(H + (size_t)row0 * 128);
        for (int i = tid; i < GEMM_TILE * 32; i += 256)
            if (row0 + (i >> 5) < N_NODES) ((float4*)sH)[i] = gH[i];
        __syncthreads();

        unsigned long long acc[4][4];
#pragma unroll
        for (int r = 0; r < 4; r++) {
            acc[r][0] = bv01.x; acc[r][1] = bv01.y;
            acc[r][2] = bv23.x; acc[r][3] = bv23.y;
        }
        const float* aH = sH + r0 * 128;
#pragma unroll 1
        for (int kk = 0; kk < 128; kk += 4) {
            float4 hv[4];
#pragma unroll
            for (int r = 0; r < 4; r++)
                hv[r] = *(const float4*)(aH + r * 128 + kk);
#pragma unroll
            for (int j = 0; j < 4; j++) {
                int k = kk + j;
                ulonglong2 wo01 = *(const ulonglong2*)(sWo + k * 128 + c0);
                ulonglong2 wo23 = *(const ulonglong2*)(sWo + k * 128 + c0 + 4);
#pragma unroll
                for (int r = 0; r < 4; r++) {
                    float a2 = (j == 0) ? hv[r].x : (j == 1) ? hv[r].y
                             : (j == 2) ? hv[r].z : hv[r].w;
                    unsigned long long p2 = pk2(a2);
                    fma2(acc[r][0], p2, wo01.x);
                    fma2(acc[r][1], p2, wo01.y);
                    fma2(acc[r][2], p2, wo23.x);
                    fma2(acc[r][3], p2, wo23.y);
                }
            }
        }
#pragma unroll
        for (int r = 0; r < 4; r++) {
            int grow = row0 + r0 + r;
            if (grow < N_NODES) {
                float2 f0 = up2(acc[r][0]);
                float2 f1 = up2(acc[r][1]);
                float2 f2 = up2(acc[r][2]);
                float2 f3 = up2(acc[r][3]);
                float4* dst = (float4*)(O + (size_t)grow * 128 + c0);
                dst[0] = make_float4(f0.x, f0.y, f1.x, f1.y);
                dst[1] = make_float4(f2.x, f2.y, f3.x, f3.y);
            }
        }
    }
}

// O = relu(agg @ Wr + O); also emits fp16 mirror Oh when non-null
__global__ void __launch_bounds__(256, 1)
k_gemm_agg(const float* __restrict__ Wr, float* __restrict__ O,
           __half* __restrict__ Oh) {
    extern __shared__ float sm[];
    float* sWr = sm;
    float* sA  = sm + 16384;
    const float* A = g_agg;

    int tid = threadIdx.x;
    for (int i = tid; i < 4096; i += 256)
        ((float4*)sWr)[i] = ((const float4*)Wr)[i];

    int c0 = (tid & 15) * 8;
    int r0 = (tid >> 4) * 4;

    for (int tile = blockIdx.x; tile < GEMM_NT; tile += gridDim.x) {
        int row0 = tile * GEMM_TILE;
        __syncthreads();
        const float4* gA = (const float4*)(A + (size_t)row0 * 128);
        for (int i = tid; i < GEMM_TILE * 32; i += 256)
            if (row0 + (i >> 5) < N_NODES) ((float4*)sA)[i] = gA[i];
        __syncthreads();

        unsigned long long acc[4][4];
#pragma unroll
        for (int r = 0; r < 4; r++) {
            int grow = row0 + r0 + r;
            if (grow < N_NODES) {
                const float4* po = (const float4*)(O + (size_t)grow * 128 + c0);
                float4 p0 = po[0], p1 = po[1];
                unsigned long long u;
                asm("mov.b64 %0, {%1, %2};" : "=l"(u) : "f"(p0.x), "f"(p0.y)); acc[r][0] = u;
                asm("mov.b64 %0, {%1, %2};" : "=l"(u) : "f"(p0.z), "f"(p0.w)); acc[r][1] = u;
                asm("mov.b64 %0, {%1, %2};" : "=l"(u) : "f"(p1.x), "f"(p1.y)); acc[r][2] = u;
                asm("mov.b64 %0, {%1, %2};" : "=l"(u) : "f"(p1.z), "f"(p1.w)); acc[r][3] = u;
            } else {
                acc[r][0] = acc[r][1] = acc[r][2] = acc[r][3] = 0ull;
            }
        }
        const float* aA = sA + r0 * 128;
#pragma unroll 1
        for (int kk = 0; kk < 128; kk += 4) {
            float4 av[4];
#pragma unroll
            for (int r = 0; r < 4; r++)
                av[r] = *(const float4*)(aA + r * 128 + kk);
#pragma unroll
            for (int j = 0; j < 4; j++) {
                int k = kk + j;
                ulonglong2 wr01 = *(const ulonglong2*)(sWr + k * 128 + c0);
                ulonglong2 wr23 = *(const ulonglong2*)(sWr + k * 128 + c0 + 4);
#pragma unroll
                for (int r = 0; r < 4; r++) {
                    float a1 = (j == 0) ? av[r].x : (j == 1) ? av[r].y
                             : (j == 2) ? av[r].z : av[r].w;
                    unsigned long long p1 = pk2(a1);
                    fma2(acc[r][0], p1, wr01.x);
                    fma2(acc[r][1], p1, wr01.y);
                    fma2(acc[r][2], p1, wr23.x);
                    fma2(acc[r][3], p1, wr23.y);
                }
            }
        }
#pragma unroll
        for (int r = 0; r < 4; r++) {
            int grow = row0 + r0 + r;
            if (grow < N_NODES) {
                float2 f0 = up2(acc[r][0]);
                float2 f1 = up2(acc[r][1]);
                float2 f2 = up2(acc[r][2]);
                float2 f3 = up2(acc[r][3]);
                float4 o0, o1;
                o0.x = fmaxf(f0.x, 0.f); o0.y = fmaxf(f0.y, 0.f);
                o0.z = fmaxf(f1.x, 0.f); o0.w = fmaxf(f1.y, 0.f);
                o1.x = fmaxf(f2.x, 0.f); o1.y = fmaxf(f2.y, 0.f);
                o1.z = fmaxf(f3.x, 0.f); o1.w = fmaxf(f3.y, 0.f);
                float4* dst = (float4*)(O + (size_t)grow * 128 + c0);
                dst[0] = o0;
                dst[1] = o1;
                if (Oh) {
                    __half2 q0 = __floats2half2_rn(o0.x, o0.y);
                    __half2 q1 = __floats2half2_rn(o0.z, o0.w);
                    __half2 q2 = __floats2half2_rn(o1.x, o1.y);
                    __half2 q3 = __floats2half2_rn(o1.z, o1.w);
                    uint4 u;
                    u.x = *(unsigned int*)&q0;
                    u.y = *(unsigned int*)&q1;
                    u.z = *(unsigned int*)&q2;
                    u.w = *(unsigned int*)&q3;
                    *(uint4*)(Oh + (size_t)grow * 128 + c0) = u;
                }
            }
        }
    }
}

// ---------------- pooling ----------------
__device__ __forceinline__ void pool_flush(int gph, int lane, float4 mx, float4 sm) {
    int base = gph * FDIM + lane * 4;
    atomicMax(&g_gmax[base + 0], __float_as_int(mx.x));
    atomicMax(&g_gmax[base + 1], __float_as_int(mx.y));
    atomicMax(&g_gmax[base + 2], __float_as_int(mx.z));
    atomicMax(&g_gmax[base + 3], __float_as_int(mx.w));
    atomicAdd(&g_gsum[base + 0], sm.x);
    atomicAdd(&g_gsum[base + 1], sm.y);
    atomicAdd(&g_gsum[base + 2], sm.z);
    atomicAdd(&g_gsum[base + 3], sm.w);
}

__global__ void k_pool(const int* __restrict__ batch) {
    const float4* __restrict__ h = (const float4*)g_h0;  // layer-2 output
    int w = (blockIdx.x * blockDim.x + threadIdx.x) >> 5;
    int lane = threadIdx.x & 31;
    if (w >= N_NODES / 32) return;
    int n0 = w * 32;
    int cur = batch[n0];
    float4 mx = make_float4(0.f, 0.f, 0.f, 0.f);
    float4 sm = make_float4(0.f, 0.f, 0.f, 0.f);
    for (int i = 0; i < 32; i++) {
        int n = n0 + i;
        int b = batch[n];
        if (b != cur) {
            pool_flush(cur, lane, mx, sm);
            mx = make_float4(0.f, 0.f, 0.f, 0.f);
            sm = make_float4(0.f, 0.f, 0.f, 0.f);
            cur = b;
        }
        float4 v = h[(size_t)n * 32 + lane];
        mx.x = fmaxf(mx.x, v.x); mx.y = fmaxf(mx.y, v.y);
        mx.z = fmaxf(mx.z, v.z); mx.w = fmaxf(mx.w, v.w);
        sm.x += v.x; sm.y += v.y; sm.z += v.z; sm.w += v.w;
    }
    pool_flush(cur, lane, mx, sm);
}

// ---------------- head: one block per graph, then softmax ----------------
__global__ void k_headz(const int* __restrict__ batch,
                        const float* __restrict__ lw1, const float* __restrict__ lb1,
                        const float* __restrict__ lw2, const float* __restrict__ lb2,
                        const float* __restrict__ lw3, const float* __restrict__ lb3) {
    __shared__ float m1[128];
    __shared__ float m2[64];
    __shared__ int bnd[2];
    int g = blockIdx.x;
    int tid = threadIdx.x;

    if (tid < 2) {
        int target = g + tid;
        int lo = 0, hi = N_NODES;
        while (lo < hi) {
            int mid = (lo + hi) >> 1;
            if (batch[mid] < target) lo = mid + 1; else hi = mid;
        }
        bnd[tid] = lo;
    }
    __syncthreads();

    {
        int cnt = bnd[1] - bnd[0];
        float inv = 1.0f / (float)(cnt > 1 ? cnt : 1);
        int c = tid;
        float acc = lb1[c];
#pragma unroll 4
        for (int k = 0; k < 128; k++)
            acc += __int_as_float(g_gmax[g * 128 + k]) * lw1[k * 128 + c];
#pragma unroll 4
        for (int k = 0; k < 128; k++)
            acc += (g_gsum[g * 128 + k] * inv) * lw1[(128 + k) * 128 + c];
        m1[c] = fmaxf(acc, 0.f);
    }
    __syncthreads();

    if (tid < 64) {
        int c = tid;
        float acc = lb2[c];
#pragma unroll 4
        for (int k = 0; k < 128; k++) acc += m1[k] * lw2[k * 64 + c];
        m2[c] = fmaxf(acc, 0.f);
    }
    __syncthreads();

    if (tid < NL) {
        int l = tid;
        float acc = lb3[l];
#pragma unroll 4
        for (int k = 0; k < 64; k++) acc += m2[k] * lw3[k * NL + l];
        g_z[g * NL + l] = acc;
    }
}

__global__ void k_softmax(float* __restrict__ out) {
    int l = threadIdx.x;
    if (l >= NL) return;
    float m = -1e30f;
    for (int g = 0; g < NG; g++) m = fmaxf(m, g_z[g * NL + l]);
    float s = 0.f;
    for (int g = 0; g < NG; g++) s += expf(g_z[g * NL + l] - m);
    float ls = m + logf(s);
    for (int g = 0; g < NG; g++) out[g * NL + l] = g_z[g * NL + l] - ls;
}

// ---------------- launch (R6 topology verbatim) ----------------
extern "C" void kernel_launch(void* const* d_in, const int* in_sizes, int n_in,
                              void* d_out, int out_size) {
    const int*   x       = (const int*)d_in[0];
    const int*   ei      = (const int*)d_in[1];
    const int*   batch   = (const int*)d_in[2];
    const float* emb     = (const float*)d_in[3];
    const float* w1_rel  = (const float*)d_in[4];
    const float* w1_root = (const float*)d_in[5];
    const float* b1      = (const float*)d_in[6];
    const float* w2_rel  = (const float*)d_in[7];
    const float* w2_root = (const float*)d_in[8];
    const float* b2      = (const float*)d_in[9];
    const float* lw1     = (const float*)d_in[10];
    const float* lb1     = (const float*)d_in[11];
    const float* lw2     = (const float*)d_in[12];
    const float* lb2     = (const float*)d_in[13];
    const float* lw3     = (const float*)d_in[14];
    const float* lb3     = (const float*)d_in[15];
    const int* src = ei;
    const int* dst = ei + N_EDGES;
    float* out = (float*)d_out;

    float *h0, *h1;
    __half *h0h, *h1h;
    void *p_deg, *p_gmax, *p_gsum;
    cudaGetSymbolAddress((void**)&h0, g_h0);
    cudaGetSymbolAddress((void**)&h1, g_h1);
    cudaGetSymbolAddress((void**)&h0h, g_h0h);
    cudaGetSymbolAddress((void**)&h1h, g_h1h);
    cudaGetSymbolAddress(&p_deg, g_deg);
    cudaGetSymbolAddress(&p_gmax, g_gmax);
    cudaGetSymbolAddress(&p_gsum, g_gsum);

    cudaFuncSetAttribute(k_gemm_root, cudaFuncAttributeMaxDynamicSharedMemorySize, HGEMM_SMEM);
    cudaFuncSetAttribute(k_gemm_agg, cudaFuncAttributeMaxDynamicSharedMemorySize, HGEMM_SMEM);

    cudaStream_t s2;
    cudaStreamCreateWithFlags(&s2, cudaStreamNonBlocking);
    cudaEvent_t ev[6];
    for (int i = 0; i < 6; i++) cudaEventCreateWithFlags(&ev[i], cudaEventDisableTiming);

    cudaMemsetAsync(p_deg, 0, N_NODES * sizeof(int));
    cudaMemsetAsync(p_gmax, 0, NG * FDIM * sizeof(int));
    cudaMemsetAsync(p_gsum, 0, NG * FDIM * sizeof(float));

    // fork: gather on s2, CSR chain on default stream (R6 pattern)
    cudaEventRecord(ev[0], 0);
    cudaStreamWaitEvent(s2, ev[0], 0);
    k_gather<<<12500, 256, 0, s2>>>(x, (const float4*)emb);

    k_count<<<N_EDGES / 256, 256>>>(dst);
    k_scan1<<<SCAN_NB, 256>>>();
    k_scan23<<<SCAN_NB, 256>>>();
    k_fill<<<N_EDGES / 256, 256>>>(src, dst);

    cudaEventRecord(ev[1], s2);
    cudaStreamWaitEvent(0, ev[1], 0);

    // ---- layer 1: aggregate(h0h) || gemm_root(h0@Wo) — shared layer data ----
    cudaEventRecord(ev[2], 0);
    cudaStreamWaitEvent(s2, ev[2], 0);
    k_gemm_root<<<148, 256, HGEMM_SMEM, s2>>>(w1_root, b1, h0, h1);
    k_aggregate<<<12500, 256>>>((const uint2*)h0h);
    cudaEventRecord(ev[3], s2);
    cudaStreamWaitEvent(0, ev[3], 0);
    k_gemm_agg<<<148, 256, HGEMM_SMEM>>>(w1_rel, h1, h1h);

    // ---- layer 2 ----
    cudaEventRecord(ev[4], 0);
    cudaStreamWaitEvent(s2, ev[4], 0);
    k_gemm_root<<<148, 256, HGEMM_SMEM, s2>>>(w2_root, b2, h1, h0);
    k_aggregate<<<12500, 256>>>((const uint2*)h1h);
    cudaEventRecord(ev[5], s2);
    cudaStreamWaitEvent(0, ev[5], 0);
    k_gemm_agg<<<148, 256, HGEMM_SMEM>>>(w2_rel, h0, (__half*)0);

    // pooling + head
    k_pool<<<SCAN_NB, 256>>>(batch);
    k_headz<<<NG, 128>>>(batch, lw1, lb1, lw2, lb2, lw3, lb3);
    k_softmax<<<1, 32>>>(out);
}

// round 13
// speedup vs baseline: 1.4341x; 1.0004x over previous
#include <cuda_runtime.h>
#include <cuda_fp16.h>
#include <math.h>

#define N_NODES 100000
#define N_EDGES 1600000
#define FDIM 128
#define NG 64
#define NL 20
#define SCAN_NB 391   // ceil(100000/256)

// ---------------- device scratch ----------------
__device__ float  g_h0[N_NODES * FDIM];
__device__ float  g_h1[N_NODES * FDIM];
__device__ __half g_h0h[N_NODES * FDIM];   // fp16 mirror for gather
__device__ __half g_h1h[N_NODES * FDIM];   // fp16 mirror for gather
__device__ float  g_agg[N_NODES * FDIM];
__device__ int    g_deg[N_NODES];
__device__ int    g_rowstart[N_NODES + 1];
__device__ int    g_cursor[N_NODES];
__device__ int    g_esrc[N_EDGES];
__device__ int    g_blocksums[512];
__device__ int    g_gmax[NG * FDIM];  // float bits; relu outputs >= 0
__device__ float  g_gsum[NG * FDIM];
__device__ float  g_z[NG * NL];

// ---------------- f32x2 helpers (FFMA2 path, PTX-only) ----------------
__device__ __forceinline__ unsigned long long pk2(float a) {
    unsigned long long r;
    asm("mov.b64 %0, {%1, %1};" : "=l"(r) : "f"(a));
    return r;
}
__device__ __forceinline__ void fma2(unsigned long long& d, unsigned long long a,
                                     unsigned long long b) {
    asm("fma.rn.f32x2 %0, %1, %2, %0;" : "+l"(d) : "l"(a), "l"(b));
}
__device__ __forceinline__ float2 up2(unsigned long long v) {
    float2 f;
    asm("mov.b64 {%0, %1}, %2;" : "=f"(f.x), "=f"(f.y) : "l"(v));
    return f;
}

// ---------------- CSR build (R6 exact: NO hot-counter atomics) ----------------
__global__ void k_count(const int* __restrict__ dst) {
    int e = blockIdx.x * blockDim.x + threadIdx.x;
    if (e < N_EDGES) atomicAdd(&g_deg[dst[e]], 1);
}

__device__ __forceinline__ int block_scan_inc(int v, int* warpbuf) {
    int tid = threadIdx.x, lane = tid & 31, wid = tid >> 5;
#pragma unroll
    for (int off = 1; off < 32; off <<= 1) {
        int t = __shfl_up_sync(0xffffffffu, v, off);
        if (lane >= off) v += t;
    }
    if (lane == 31) warpbuf[wid] = v;
    __syncthreads();
    if (wid == 0) {
        int nw = blockDim.x >> 5;
        int w = (lane < nw) ? warpbuf[lane] : 0;
#pragma unroll
        for (int off = 1; off < 32; off <<= 1) {
            int t = __shfl_up_sync(0xffffffffu, w, off);
            if (lane >= off) w += t;
        }
        warpbuf[lane] = w;
    }
    __syncthreads();
    return v + (wid > 0 ? warpbuf[wid - 1] : 0);
}

__global__ void k_scan1() {
    __shared__ int wb[32];
    int i = blockIdx.x * blockDim.x + threadIdx.x;
    int v = (i < N_NODES) ? g_deg[i] : 0;
    int inc = block_scan_inc(v, wb);
    if (threadIdx.x == blockDim.x - 1) g_blocksums[blockIdx.x] = inc;
}

__global__ void k_scan23() {
    __shared__ int wb[32];
    __shared__ int s_off;
    int tid = threadIdx.x;
    int i = blockIdx.x * blockDim.x + tid;
    int v = (i < N_NODES) ? g_deg[i] : 0;
    int inc = block_scan_inc(v, wb);
    if (tid < 32) {
        int p = 0;
        for (int j = tid; j < blockIdx.x; j += 32) p += g_blocksums[j];
#pragma unroll
        for (int off = 16; off > 0; off >>= 1)
            p += __shfl_down_sync(0xffffffffu, p, off);
        if (tid == 0) s_off = p;
    }
    __syncthreads();
    if (i < N_NODES) {
        int ex = s_off + inc - v;
        g_rowstart[i] = ex;
        g_cursor[i] = ex;
        if (i == N_NODES - 1) g_rowstart[N_NODES] = ex + v;
    }
}

__global__ void k_fill(const int* __restrict__ src, const int* __restrict__ dst) {
    int e = blockIdx.x * blockDim.x + threadIdx.x;
    if (e >= N_EDGES) return;
    int d = dst[e];
    int pos = atomicAdd(&g_cursor[d], 1);
    g_esrc[pos] = src[e];
}

// ---------------- embedding gather: fp32 + fp16 mirror ----------------
__global__ void k_gather(const int* __restrict__ x, const float4* __restrict__ emb) {
    int idx = blockIdx.x * blockDim.x + threadIdx.x;
    if (idx >= N_NODES * 32) return;
    int node = idx >> 5;
    int c = idx & 31;
    float4 v = emb[(size_t)x[node] * 32 + c];
    ((float4*)g_h0)[idx] = v;
    __half2 p0 = __floats2half2_rn(v.x, v.y);
    __half2 p1 = __floats2half2_rn(v.z, v.w);
    uint2 u;
    u.x = *(unsigned int*)&p0;
    u.y = *(unsigned int*)&p1;
    ((uint2*)g_h0h)[idx] = u;
}

// ---- aggregation: warp/node, MLP=4 unrolled shfl, fp16 input, fp32 accum ----
__device__ __forceinline__ void agg_accum4h(float4& acc, const uint2* __restrict__ tab,
                                            int a0, int a1, int a2, int a3, int lane) {
    uint2 u0 = tab[(size_t)a0 * 32 + lane];
    uint2 u1 = tab[(size_t)a1 * 32 + lane];
    uint2 u2 = tab[(size_t)a2 * 32 + lane];
    uint2 u3 = tab[(size_t)a3 * 32 + lane];
    float2 f;
    f = __half22float2(*(__half2*)&u0.x); acc.x += f.x; acc.y += f.y;
    f = __half22float2(*(__half2*)&u0.y); acc.z += f.x; acc.w += f.y;
    f = __half22float2(*(__half2*)&u1.x); acc.x += f.x; acc.y += f.y;
    f = __half22float2(*(__half2*)&u1.y); acc.z += f.x; acc.w += f.y;
    f = __half22float2(*(__half2*)&u2.x); acc.x += f.x; acc.y += f.y;
    f = __half22float2(*(__half2*)&u2.y); acc.z += f.x; acc.w += f.y;
    f = __half22float2(*(__half2*)&u3.x); acc.x += f.x; acc.y += f.y;
    f = __half22float2(*(__half2*)&u3.y); acc.z += f.x; acc.w += f.y;
}

__global__ void k_aggregate(const uint2* __restrict__ hin2) {
    int w = (blockIdx.x * blockDim.x + threadIdx.x) >> 5;
    int lane = threadIdx.x & 31;
    if (w >= N_NODES) return;
    int s = g_rowstart[w], e = g_rowstart[w + 1];
    float4 acc = make_float4(0.f, 0.f, 0.f, 0.f);
    for (int i = s; i < e; i += 32) {
        int cnt = min(32, e - i);
        int xs = g_esrc[i + ((lane < cnt) ? lane : 0)];
        if (cnt == 32) {
#pragma unroll
            for (int j = 0; j < 32; j += 4) {
                int a0 = __shfl_sync(0xffffffffu, xs, j);
                int a1 = __shfl_sync(0xffffffffu, xs, j + 1);
                int a2 = __shfl_sync(0xffffffffu, xs, j + 2);
                int a3 = __shfl_sync(0xffffffffu, xs, j + 3);
                agg_accum4h(acc, hin2, a0, a1, a2, a3, lane);
            }
        } else {
            int j = 0;
            for (; j + 4 <= cnt; j += 4) {
                int a0 = __shfl_sync(0xffffffffu, xs, j);
                int a1 = __shfl_sync(0xffffffffu, xs, j + 1);
                int a2 = __shfl_sync(0xffffffffu, xs, j + 2);
                int a3 = __shfl_sync(0xffffffffu, xs, j + 3);
                agg_accum4h(acc, hin2, a0, a1, a2, a3, lane);
            }
            for (; j < cnt; j++) {
                int a = __shfl_sync(0xffffffffu, xs, j);
                uint2 u = hin2[(size_t)a * 32 + lane];
                float2 f0 = __half22float2(*(__half2*)&u.x);
                float2 f1 = __half22float2(*(__half2*)&u.y);
                acc.x += f0.x; acc.y += f0.y; acc.z += f1.x; acc.w += f1.y;
            }
        }
    }
    ((float4*)g_agg)[(size_t)w * 32 + lane] = acc;
}

// ---------------- split FFMA2 GEMMs (R6-proven) ----------------
#define GEMM_TILE 64
#define GEMM_NT   1563  // ceil(100000/64)
#define HGEMM_SMEM ((16384 + GEMM_TILE * 128) * 4)

// O = H @ Wo + b   (root half; overlaps aggregation reading the same layer)
__global__ void __launch_bounds__(256, 1)
k_gemm_root(const float* __restrict__ Wo, const float* __restrict__ bias,
            const float* __restrict__ H, float* __restrict__ O) {
    extern __shared__ float sm[];
    float* sWo = sm;
    float* sH  = sm + 16384;

    int tid = threadIdx.x;
    for (int i = tid; i < 4096; i += 256)
        ((float4*)sWo)[i] = ((const float4*)Wo)[i];

    int c0 = (tid & 15) * 8;
    int r0 = (tid >> 4) * 4;
    ulonglong2 bv01 = *(const ulonglong2*)(bias + c0);
    ulonglong2 bv23 = *(const ulonglong2*)(bias + c0 + 4);

    for (int tile = blockIdx.x; tile < GEMM_NT; tile += gridDim.x) {
        int row0 = tile * GEMM_TILE;
        __syncthreads();
        const float4* gH = (const float4*)(H + (size_t)row0 * 128);
        for (int i = tid; i < GEMM_TILE * 32; i += 256)
            if (row0 + (i >> 5) < N_NODES) ((float4*)sH)[i] = gH[i];
        __syncthreads();

        unsigned long long acc[4][4];
#pragma unroll
        for (int r = 0; r < 4; r++) {
            acc[r][0] = bv01.x; acc[r][1] = bv01.y;
            acc[r][2] = bv23.x; acc[r][3] = bv23.y;
        }
        const float* aH = sH + r0 * 128;
#pragma unroll 1
        for (int kk = 0; kk < 128; kk += 4) {
            float4 hv[4];
#pragma unroll
            for (int r = 0; r < 4; r++)
                hv[r] = *(const float4*)(aH + r * 128 + kk);
#pragma unroll
            for (int j = 0; j < 4; j++) {
                int k = kk + j;
                ulonglong2 wo01 = *(const ulonglong2*)(sWo + k * 128 + c0);
                ulonglong2 wo23 = *(const ulonglong2*)(sWo + k * 128 + c0 + 4);
#pragma unroll
                for (int r = 0; r < 4; r++) {
                    float a2 = (j == 0) ? hv[r].x : (j == 1) ? hv[r].y
                             : (j == 2) ? hv[r].z : hv[r].w;
                    unsigned long long p2 = pk2(a2);
                    fma2(acc[r][0], p2, wo01.x);
                    fma2(acc[r][1], p2, wo01.y);
                    fma2(acc[r][2], p2, wo23.x);
                    fma2(acc[r][3], p2, wo23.y);
                }
            }
        }
#pragma unroll
        for (int r = 0; r < 4; r++) {
            int grow = row0 + r0 + r;
            if (grow < N_NODES) {
                float2 f0 = up2(acc[r][0]);
                float2 f1 = up2(acc[r][1]);
                float2 f2 = up2(acc[r][2]);
                float2 f3 = up2(acc[r][3]);
                float4* dst = (float4*)(O + (size_t)grow * 128 + c0);
                dst[0] = make_float4(f0.x, f0.y, f1.x, f1.y);
                dst[1] = make_float4(f2.x, f2.y, f3.x, f3.y);
            }
        }
    }
}

// O = relu(agg @ Wr + O); also emits fp16 mirror Oh when non-null
__global__ void __launch_bounds__(256, 1)
k_gemm_agg(const float* __restrict__ Wr, float* __restrict__ O,
           __half* __restrict__ Oh) {
    extern __shared__ float sm[];
    float* sWr = sm;
    float* sA  = sm + 16384;
    const float* A = g_agg;

    int tid = threadIdx.x;
    for (int i = tid; i < 4096; i += 256)
        ((float4*)sWr)[i] = ((const float4*)Wr)[i];

    int c0 = (tid & 15) * 8;
    int r0 = (tid >> 4) * 4;

    for (int tile = blockIdx.x; tile < GEMM_NT; tile += gridDim.x) {
        int row0 = tile * GEMM_TILE;
        __syncthreads();
        const float4* gA = (const float4*)(A + (size_t)row0 * 128);
        for (int i = tid; i < GEMM_TILE * 32; i += 256)
            if (row0 + (i >> 5) < N_NODES) ((float4*)sA)[i] = gA[i];
        __syncthreads();

        unsigned long long acc[4][4];
#pragma unroll
        for (int r = 0; r < 4; r++) {
            int grow = row0 + r0 + r;
            if (grow < N_NODES) {
                const float4* po = (const float4*)(O + (size_t)grow * 128 + c0);
                float4 p0 = po[0], p1 = po[1];
                unsigned long long u;
                asm("mov.b64 %0, {%1, %2};" : "=l"(u) : "f"(p0.x), "f"(p0.y)); acc[r][0] = u;
                asm("mov.b64 %0, {%1, %2};" : "=l"(u) : "f"(p0.z), "f"(p0.w)); acc[r][1] = u;
                asm("mov.b64 %0, {%1, %2};" : "=l"(u) : "f"(p1.x), "f"(p1.y)); acc[r][2] = u;
                asm("mov.b64 %0, {%1, %2};" : "=l"(u) : "f"(p1.z), "f"(p1.w)); acc[r][3] = u;
            } else {
                acc[r][0] = acc[r][1] = acc[r][2] = acc[r][3] = 0ull;
            }
        }
        const float* aA = sA + r0 * 128;
#pragma unroll 1
        for (int kk = 0; kk < 128; kk += 4) {
            float4 av[4];
#pragma unroll
            for (int r = 0; r < 4; r++)
                av[r] = *(const float4*)(aA + r * 128 + kk);
#pragma unroll
            for (int j = 0; j < 4; j++) {
                int k = kk + j;
                ulonglong2 wr01 = *(const ulonglong2*)(sWr + k * 128 + c0);
                ulonglong2 wr23 = *(const ulonglong2*)(sWr + k * 128 + c0 + 4);
#pragma unroll
                for (int r = 0; r < 4; r++) {
                    float a1 = (j == 0) ? av[r].x : (j == 1) ? av[r].y
                             : (j == 2) ? av[r].z : av[r].w;
                    unsigned long long p1 = pk2(a1);
                    fma2(acc[r][0], p1, wr01.x);
                    fma2(acc[r][1], p1, wr01.y);
                    fma2(acc[r][2], p1, wr23.x);
                    fma2(acc[r][3], p1, wr23.y);
                }
            }
        }
#pragma unroll
        for (int r = 0; r < 4; r++) {
            int grow = row0 + r0 + r;
            if (grow < N_NODES) {
                float2 f0 = up2(acc[r][0]);
                float2 f1 = up2(acc[r][1]);
                float2 f2 = up2(acc[r][2]);
                float2 f3 = up2(acc[r][3]);
                float4 o0, o1;
                o0.x = fmaxf(f0.x, 0.f); o0.y = fmaxf(f0.y, 0.f);
                o0.z = fmaxf(f1.x, 0.f); o0.w = fmaxf(f1.y, 0.f);
                o1.x = fmaxf(f2.x, 0.f); o1.y = fmaxf(f2.y, 0.f);
                o1.z = fmaxf(f3.x, 0.f); o1.w = fmaxf(f3.y, 0.f);
                float4* dst = (float4*)(O + (size_t)grow * 128 + c0);
                dst[0] = o0;
                dst[1] = o1;
                if (Oh) {
                    __half2 q0 = __floats2half2_rn(o0.x, o0.y);
                    __half2 q1 = __floats2half2_rn(o0.z, o0.w);
                    __half2 q2 = __floats2half2_rn(o1.x, o1.y);
                    __half2 q3 = __floats2half2_rn(o1.z, o1.w);
                    uint4 u;
                    u.x = *(unsigned int*)&q0;
                    u.y = *(unsigned int*)&q1;
                    u.z = *(unsigned int*)&q2;
                    u.w = *(unsigned int*)&q3;
                    *(uint4*)(Oh + (size_t)grow * 128 + c0) = u;
                }
            }
        }
    }
}

// ---------------- pooling ----------------
__device__ __forceinline__ void pool_flush(int gph, int lane, float4 mx, float4 sm) {
    int base = gph * FDIM + lane * 4;
    atomicMax(&g_gmax[base + 0], __float_as_int(mx.x));
    atomicMax(&g_gmax[base + 1], __float_as_int(mx.y));
    atomicMax(&g_gmax[base + 2], __float_as_int(mx.z));
    atomicMax(&g_gmax[base + 3], __float_as_int(mx.w));
    atomicAdd(&g_gsum[base + 0], sm.x);
    atomicAdd(&g_gsum[base + 1], sm.y);
    atomicAdd(&g_gsum[base + 2], sm.z);
    atomicAdd(&g_gsum[base + 3], sm.w);
}

__global__ void k_pool(const int* __restrict__ batch) {
    const float4* __restrict__ h = (const float4*)g_h0;  // layer-2 output
    int w = (blockIdx.x * blockDim.x + threadIdx.x) >> 5;
    int lane = threadIdx.x & 31;
    if (w >= N_NODES / 32) return;
    int n0 = w * 32;
    int cur = batch[n0];
    float4 mx = make_float4(0.f, 0.f, 0.f, 0.f);
    float4 sm = make_float4(0.f, 0.f, 0.f, 0.f);
    for (int i = 0; i < 32; i++) {
        int n = n0 + i;
        int b = batch[n];
        if (b != cur) {
            pool_flush(cur, lane, mx, sm);
            mx = make_float4(0.f, 0.f, 0.f, 0.f);
            sm = make_float4(0.f, 0.f, 0.f, 0.f);
            cur = b;
        }
        float4 v = h[(size_t)n * 32 + lane];
        mx.x = fmaxf(mx.x, v.x); mx.y = fmaxf(mx.y, v.y);
        mx.z = fmaxf(mx.z, v.z); mx.w = fmaxf(mx.w, v.w);
        sm.x += v.x; sm.y += v.y; sm.z += v.z; sm.w += v.w;
    }
    pool_flush(cur, lane, mx, sm);
}

// ---------------- head: one block per graph, then softmax ----------------
__global__ void k_headz(const int* __restrict__ batch,
                        const float* __restrict__ lw1, const float* __restrict__ lb1,
                        const float* __restrict__ lw2, const float* __restrict__ lb2,
                        const float* __restrict__ lw3, const float* __restrict__ lb3) {
    __shared__ float m1[128];
    __shared__ float m2[64];
    __shared__ int bnd[2];
    int g = blockIdx.x;
    int tid = threadIdx.x;

    if (tid < 2) {
        int target = g + tid;
        int lo = 0, hi = N_NODES;
        while (lo < hi) {
            int mid = (lo + hi) >> 1;
            if (batch[mid] < target) lo = mid + 1; else hi = mid;
        }
        bnd[tid] = lo;
    }
    __syncthreads();

    {
        int cnt = bnd[1] - bnd[0];
        float inv = 1.0f / (float)(cnt > 1 ? cnt : 1);
        int c = tid;
        float acc = lb1[c];
#pragma unroll 4
        for (int k = 0; k < 128; k++)
            acc += __int_as_float(g_gmax[g * 128 + k]) * lw1[k * 128 + c];
#pragma unroll 4
        for (int k = 0; k < 128; k++)
            acc += (g_gsum[g * 128 + k] * inv) * lw1[(128 + k) * 128 + c];
        m1[c] = fmaxf(acc, 0.f);
    }
    __syncthreads();

    if (tid < 64) {
        int c = tid;
        float acc = lb2[c];
#pragma unroll 4
        for (int k = 0; k < 128; k++) acc += m1[k] * lw2[k * 64 + c];
        m2[c] = fmaxf(acc, 0.f);
    }
    __syncthreads();

    if (tid < NL) {
        int l = tid;
        float acc = lb3[l];
#pragma unroll 4
        for (int k = 0; k < 64; k++) acc += m2[k] * lw3[k * NL + l];
        g_z[g * NL + l] = acc;
    }
}

__global__ void k_softmax(float* __restrict__ out) {
    int l = threadIdx.x;
    if (l >= NL) return;
    float m = -1e30f;
    for (int g = 0; g < NG; g++) m = fmaxf(m, g_z[g * NL + l]);
    float s = 0.f;
    for (int g = 0; g < NG; g++) s += expf(g_z[g * NL + l] - m);
    float ls = m + logf(s);
    for (int g = 0; g < NG; g++) out[g * NL + l] = g_z[g * NL + l] - ls;
}

// ---------------- launch (R12 topology verbatim) ----------------
extern "C" void kernel_launch(void* const* d_in, const int* in_sizes, int n_in,
                              void* d_out, int out_size) {
    const int*   x       = (const int*)d_in[0];
    const int*   ei      = (const int*)d_in[1];
    const int*   batch   = (const int*)d_in[2];
    const float* emb     = (const float*)d_in[3];
    const float* w1_rel  = (const float*)d_in[4];
    const float* w1_root = (const float*)d_in[5];
    const float* b1      = (const float*)d_in[6];
    const float* w2_rel  = (const float*)d_in[7];
    const float* w2_root = (const float*)d_in[8];
    const float* b2      = (const float*)d_in[9];
    const float* lw1     = (const float*)d_in[10];
    const float* lb1     = (const float*)d_in[11];
    const float* lw2     = (const float*)d_in[12];
    const float* lb2     = (const float*)d_in[13];
    const float* lw3     = (const float*)d_in[14];
    const float* lb3     = (const float*)d_in[15];
    const int* src = ei;
    const int* dst = ei + N_EDGES;
    float* out = (float*)d_out;

    float *h0, *h1;
    __half *h0h, *h1h;
    void *p_deg, *p_gmax, *p_gsum;
    cudaGetSymbolAddress((void**)&h0, g_h0);
    cudaGetSymbolAddress((void**)&h1, g_h1);
    cudaGetSymbolAddress((void**)&h0h, g_h0h);
    cudaGetSymbolAddress((void**)&h1h, g_h1h);
    cudaGetSymbolAddress(&p_deg, g_deg);
    cudaGetSymbolAddress(&p_gmax, g_gmax);
    cudaGetSymbolAddress(&p_gsum, g_gsum);

    cudaFuncSetAttribute(k_gemm_root, cudaFuncAttributeMaxDynamicSharedMemorySize, HGEMM_SMEM);
    cudaFuncSetAttribute(k_gemm_agg, cudaFuncAttributeMaxDynamicSharedMemorySize, HGEMM_SMEM);

    cudaStream_t s2;
    cudaStreamCreateWithFlags(&s2, cudaStreamNonBlocking);
    cudaEvent_t ev[6];
    for (int i = 0; i < 6; i++) cudaEventCreateWithFlags(&ev[i], cudaEventDisableTiming);

    cudaMemsetAsync(p_deg, 0, N_NODES * sizeof(int));
    cudaMemsetAsync(p_gmax, 0, NG * FDIM * sizeof(int));
    cudaMemsetAsync(p_gsum, 0, NG * FDIM * sizeof(float));

    // fork: gather on s2, CSR chain on default stream (R6 pattern)
    cudaEventRecord(ev[0], 0);
    cudaStreamWaitEvent(s2, ev[0], 0);
    k_gather<<<12500, 256, 0, s2>>>(x, (const float4*)emb);

    k_count<<<N_EDGES / 256, 256>>>(dst);
    k_scan1<<<SCAN_NB, 256>>>();
    k_scan23<<<SCAN_NB, 256>>>();
    k_fill<<<N_EDGES / 256, 256>>>(src, dst);

    cudaEventRecord(ev[1], s2);
    cudaStreamWaitEvent(0, ev[1], 0);

    // ---- layer 1: aggregate(h0h) || gemm_root(h0@Wo) — shared layer data ----
    cudaEventRecord(ev[2], 0);
    cudaStreamWaitEvent(s2, ev[2], 0);
    k_gemm_root<<<148, 256, HGEMM_SMEM, s2>>>(w1_root, b1, h0, h1);
    k_aggregate<<<12500, 256>>>((const uint2*)h0h);
    cudaEventRecord(ev[3], s2);
    cudaStreamWaitEvent(0, ev[3], 0);
    k_gemm_agg<<<148, 256, HGEMM_SMEM>>>(w1_rel, h1, h1h);

    // ---- layer 2 ----
    cudaEventRecord(ev[4], 0);
    cudaStreamWaitEvent(s2, ev[4], 0);
    k_gemm_root<<<148, 256, HGEMM_SMEM, s2>>>(w2_root, b2, h1, h0);
    k_aggregate<<<12500, 256>>>((const uint2*)h1h);
    cudaEventRecord(ev[5], s2);
    cudaStreamWaitEvent(0, ev[5], 0);
    k_gemm_agg<<<148, 256, HGEMM_SMEM>>>(w2_rel, h0, (__half*)0);

    // pooling + head
    k_pool<<<SCAN_NB, 256>>>(batch);
    k_headz<<<NG, 128>>>(batch, lw1, lb1, lw2, lb2, lw3, lb3);
    k_softmax<<<1, 32>>>(out);
}